// round 15
// baseline (speedup 1.0000x reference)
#include <cuda_runtime.h>
#include <cstdint>

// Cone-beam flat-panel forward projector, round 15.
// g_volQ[y][x][z] (z fastest, 128 MB): 4x fp16 per entry =
//   lo u32 = half2( v[z,y,x],   v[z+1,y,x]   )   (z-pair at x)
//   hi u32 = half2( v[z,y,x+1], v[z+1,y,x+1] )   (z-pair at x+1)
// 8 corners from 2 LDG.64; fp16 x/y lerp; fp32 z-lerp + accumulate.
// R15: (a) prologue stores uint4 (2 quads per STG.128, half the stores);
//      (b) 4 lanes per ray (quarter intervals), shfl_xor(8)+shfl_xor(16).
// vol in: [256,256,256] fp32 (z,y,x). out: [16,64,384] fp32.

#define NCOL 384
#define NROW 64
#define NVIEW 16
#define NSAMP 256

__device__ uint2 g_volQ[256 * 256 * 256];   // [y][x][z] fp16 quads, 128 MB

// pack two f32 -> f16x2 u32 (d = {hi, lo} per cvt semantics)
__device__ __forceinline__ unsigned int f2_to_h2(float hi, float lo) {
    unsigned int r;
    asm("cvt.rn.f16x2.f32 %0, %1, %2;" : "=r"(r) : "f"(hi), "f"(lo));
    return r;
}
// half2 (u32) -> two f32
__device__ __forceinline__ void h2_to_2f(unsigned int h2, float& lo, float& hi) {
    asm("{\n\t"
        ".reg .b16 l, h;\n\t"
        "mov.b32 {l, h}, %2;\n\t"
        "cvt.f32.f16 %0, l;\n\t"
        "cvt.f32.f16 %1, h;\n\t"
        "}" : "=f"(lo), "=f"(hi) : "r"(h2));
}
// ---- f16x2 math ----
__device__ __forceinline__ unsigned int hsub2(unsigned int a, unsigned int b) {
    unsigned int r;
    asm("sub.f16x2 %0, %1, %2;" : "=r"(r) : "r"(a), "r"(b));
    return r;
}
__device__ __forceinline__ unsigned int hfma2(unsigned int a, unsigned int b,
                                              unsigned int c) {
    unsigned int r;
    asm("fma.rn.f16x2 %0, %1, %2, %3;" : "=r"(r) : "r"(a), "r"(b), "r"(c));
    return r;
}

// prologue: vol[z][y][x] fp32 -> g_volQ[y][x][z] fp16 quads.
// Store phase emits uint4 (two consecutive z-quads) per store.
__global__ void __launch_bounds__(256)
quad_build_kernel(const float* __restrict__ vol) {
    __shared__ float ts[33][33];               // [z local 0..32][x local 0..32]
    const int z0 = blockIdx.x * 32;
    const int x0 = blockIdx.y * 32;
    const int y  = blockIdx.z;
    const int t  = threadIdx.x;                // 0..255
    const int tx = t & 31;
    const int ty = t >> 5;                     // 0..7

    #pragma unroll
    for (int i = 0; i < 32; i += 8)
        ts[ty + i][tx] = vol[((z0 + ty + i) << 16) | (y << 8) | (x0 + tx)];
    if (ty == 0) {                             // extra z row
        const int z = z0 + 32;
        ts[32][tx] = (z < 256) ? vol[(z << 16) | (y << 8) | (x0 + tx)] : 0.0f;
    }
    if (ty == 1) {                             // extra x column
        const int x = x0 + 32;
        ts[tx][32] = (x < 256) ? vol[((z0 + tx) << 16) | (y << 8) | x] : 0.0f;
    }
    if (ty == 2 && tx == 0) {                  // corner
        const int z = z0 + 32, x = x0 + 32;
        ts[32][32] = (z < 256 && x < 256) ? vol[(z << 16) | (y << 8) | x] : 0.0f;
    }
    __syncthreads();

    // store: thread -> (z-pair zq 0..15, x-col xi 0..15); two x passes.
    const int zq = t & 15;                     // z = 2*zq, 2*zq+1
    const int xi = t >> 4;                     // 0..15
    const int z  = zq * 2;
    #pragma unroll
    for (int xo = 0; xo < 32; xo += 16) {
        const int xl = xi + xo;
        uint4 w;
        w.x = f2_to_h2(ts[z + 1][xl],     ts[z][xl]);          // quad z   .x
        w.y = f2_to_h2(ts[z + 1][xl + 1], ts[z][xl + 1]);      // quad z   .y
        w.z = f2_to_h2(ts[z + 2][xl],     ts[z + 1][xl]);      // quad z+1 .x
        w.w = f2_to_h2(ts[z + 2][xl + 1], ts[z + 1][xl + 1]);  // quad z+1 .y
        reinterpret_cast<uint4*>(g_volQ)
            [(y << 15) | ((x0 + xl) << 7) | ((z0 >> 1) + zq)] = w;
    }
}

// checked scalar fetch (boundary path): lo fp16 of lo word = v[z,y,x]
__device__ __forceinline__ float fetchS(int z, int y, int x) {
    if ((unsigned)x < 256u && (unsigned)y < 256u && (unsigned)z < 256u) {
        const unsigned int w =
            __ldg((const unsigned int*)g_volQ + (((y << 16) | (x << 8) | z) << 1));
        float v;
        asm("{\n\t.reg .b16 l, h;\n\tmov.b32 {l, h}, %1;\n\tcvt.f32.f16 %0, l;\n\t}"
            : "=f"(v) : "r"(w));
        return v;
    }
    return 0.0f;
}

// cold path: out of hot-loop register allocation
__device__ __noinline__ float trilerp_checked(float x, float y, float z) {
    const float xf = floorf(x), yf = floorf(y), zf = floorf(z);
    const float fx = x - xf, fy = y - yf, fz = z - zf;
    const int x0 = (int)xf, y0 = (int)yf, z0 = (int)zf;
    const float c000 = fetchS(z0,     y0,     x0);
    const float c001 = fetchS(z0,     y0,     x0 + 1);
    const float c010 = fetchS(z0,     y0 + 1, x0);
    const float c011 = fetchS(z0,     y0 + 1, x0 + 1);
    const float c100 = fetchS(z0 + 1, y0,     x0);
    const float c101 = fetchS(z0 + 1, y0,     x0 + 1);
    const float c110 = fetchS(z0 + 1, y0 + 1, x0);
    const float c111 = fetchS(z0 + 1, y0 + 1, x0 + 1);
    const float gx = 1.0f - fx, gy = 1.0f - fy, gz = 1.0f - fz;
    const float v00 = gx * c000 + fx * c001;
    const float v01 = gx * c010 + fx * c011;
    const float v10 = gx * c100 + fx * c101;
    const float v11 = gx * c110 + fx * c111;
    const float v0  = gy * v00 + fy * v01;
    const float v1  = gy * v10 + fy * v11;
    return gz * v0 + fz * v1;
}

__global__ void __launch_bounds__(256)
proj_kernel(const float* __restrict__ angles,
            float* __restrict__ out) {
    const int tidx = blockIdx.x * blockDim.x + threadIdx.x;
    const int lane = threadIdx.x & 31;
    const int q    = lane >> 3;                      // quarter 0..3
    const int rid  = (tidx >> 5) * 8 + (lane & 7);   // 8 rays/warp, 4 lanes each
    const int row  = rid & 63;
    const int col  = (rid >> 6) % NCOL;
    const int view = rid / (64 * NCOL);

    const float DET_U = 1.2f, DET_V = 1.2f;
    const float ISO = 500.0f, SDD = 1000.0f;
    const float RAY_LEN = 1.7320508075688772f * 256.0f;
    const float DT = RAY_LEN / (float)NSAMP;   // sqrt(3)

    const float beta = angles[view];
    const float cb = cosf(beta);
    const float sb = sinf(beta);

    const float u = ((float)col - NCOL * 0.5f + 0.5f) * DET_U;
    const float v = ((float)row - NROW * 0.5f + 0.5f) * DET_V;

    const float sx = ISO * cb;
    const float sy = ISO * sb;
    float dx = -(SDD - ISO) * cb - u * sb - sx;
    float dy = -(SDD - ISO) * sb + u * cb - sy;
    float dz = v;
    const float inv = rsqrtf(dx * dx + dy * dy + dz * dz);
    dx *= inv; dy *= inv; dz *= inv;

    const float t0 = ISO - RAY_LEN * 0.5f + 0.5f * DT;

    // outer clip (all coords in (-128.5,128.5)) and inner fully-interior clip
    float tmin = -1e30f, tmax = 1e30f;
    float t2mn = -1e30f, t2mx = 1e30f;
    {
        const float s0[3] = {sx, sy, 0.0f};
        const float dd[3] = {dx, dy, dz};
        #pragma unroll
        for (int ax = 0; ax < 3; ++ax) {
            if (fabsf(dd[ax]) > 1e-12f) {
                const float r = 1.0f / dd[ax];
                float ta = (-128.5f - s0[ax]) * r;
                float tb = ( 128.5f - s0[ax]) * r;
                tmin = fmaxf(tmin, fminf(ta, tb));
                tmax = fminf(tmax, fmaxf(ta, tb));
                ta = (-127.49f - s0[ax]) * r;
                tb = ( 127.49f - s0[ax]) * r;
                t2mn = fmaxf(t2mn, fminf(ta, tb));
                t2mx = fminf(t2mx, fmaxf(ta, tb));
            } else {
                if (s0[ax] <= -128.5f  || s0[ax] >= 128.5f)  tmax = tmin - 1.0f;
                if (s0[ax] <  -127.49f || s0[ax] >  127.49f) t2mx = t2mn - 1.0f;
            }
        }
    }
    int s_lo = max((int)floorf((tmin - t0) / DT), 0);
    int s_hi = min((int)ceilf ((tmax - t0) / DT) + 1, NSAMP - 1);
    int i_lo = max((int)ceilf ((t2mn - t0) / DT), s_lo);
    int i_hi = min((int)floorf((t2mx - t0) / DT), s_hi);
    if (i_lo > i_hi) { i_lo = s_hi + 1; i_hi = s_hi; }

    const float ax0 = fmaf(t0, dx, sx) + 127.5f;
    const float ay0 = fmaf(t0, dy, sy) + 127.5f;
    const float az0 = fmaf(t0, dz, 0.0f) + 127.5f;
    const float axs = DT * dx, ays = DT * dy, azs = DT * dz;

    // quarter intervals of the interior; q0 also does head, q3 also does tail
    const int len    = i_hi + 1 - i_lo;
    const int my_ilo = i_lo + ((len * q) >> 2);
    const int my_ihi = i_lo + ((len * (q + 1)) >> 2) - 1;

    float acc = 0.0f;

    if (q == 0) {
        for (int s = s_lo; s < i_lo; ++s) {
            const float fs = (float)s;
            acc += trilerp_checked(fmaf(fs, axs, ax0), fmaf(fs, ays, ay0),
                                   fmaf(fs, azs, az0));
        }
    } else if (q == 3) {
        for (int s = i_hi + 1; s <= s_hi; ++s) {
            const float fs = (float)s;
            acc += trilerp_checked(fmaf(fs, axs, ax0), fmaf(fs, ays, ay0),
                                   fmaf(fs, azs, az0));
        }
    }

    // interior: 2x LDG.64, fp16 x+y lerp, single h2->f32, fp32 z-lerp/acc
    #pragma unroll 4
    for (int s = my_ilo; s <= my_ihi; ++s) {
        const float fs = (float)s;
        const float x = fmaf(fs, axs, ax0);
        const float y = fmaf(fs, ays, ay0);
        const float z = fmaf(fs, azs, az0);

        const float xf = floorf(x), yf = floorf(y), zf = floorf(z);
        const float fx = x - xf, fy = y - yf, fz = z - zf;

        // fused float-domain index (exact: integers < 2^24), quad strides
        const int idx = (int)fmaf(yf, 65536.0f, fmaf(xf, 256.0f, zf));

        const uint2* p = g_volQ + idx;
        const uint2 q0 = __ldg(p);             // y0   : z-pairs @ x0, x0+1
        const uint2 q1 = __ldg(p + 65536);     // y0+1 : z-pairs @ x0, x0+1

        // x-lerp in f16x2: v = a + fx*(b-a)
        const unsigned int fxh = f2_to_h2(fx, fx);
        const unsigned int v0h = hfma2(fxh, hsub2(q0.y, q0.x), q0.x);
        const unsigned int v1h = hfma2(fxh, hsub2(q1.y, q1.x), q1.x);

        // y-lerp in f16x2
        const unsigned int fyh = f2_to_h2(fy, fy);
        const unsigned int vvh = hfma2(fyh, hsub2(v1h, v0h), v0h);

        // single conversion, scalar fp32 z-lerp + accumulate
        float vlo, vhi;
        h2_to_2f(vvh, vlo, vhi);
        acc = fmaf(fz, vhi - vlo, acc + vlo);
    }

    // combine the four quarters of each ray and write once
    acc += __shfl_xor_sync(0xffffffffu, acc, 8);
    acc += __shfl_xor_sync(0xffffffffu, acc, 16);
    if (q == 0)
        out[(view * NROW + row) * NCOL + col] = acc * DT;
}

extern "C" void kernel_launch(void* const* d_in, const int* in_sizes, int n_in,
                              void* d_out, int out_size) {
    const float* img = (const float*)d_in[0];
    const float* ang = (const float*)d_in[1];
    if (n_in >= 2 && in_sizes[0] < in_sizes[1]) {
        img = (const float*)d_in[1];
        ang = (const float*)d_in[0];
    }
    float* out = (float*)d_out;

    dim3 tb(256, 1, 1);
    dim3 tg(8, 8, 256);            // (z-tiles, x-tiles, y)
    quad_build_kernel<<<tg, tb>>>(img);

    const int total_threads = NVIEW * NROW * NCOL * 4;  // 1572864 (4 lanes/ray)
    proj_kernel<<<total_threads / 256, 256>>>(ang, out);
}

// round 16
// speedup vs baseline: 1.1593x; 1.1593x over previous
#include <cuda_runtime.h>
#include <cstdint>

// Cone-beam flat-panel forward projector, round 16.
// = R14 proj kernel (best: 99.4us) + R15 uint4-store prologue (verified, 32us)
//   + float sample counter (removes per-sample I2F).
// g_volQ[y][x][z] (z fastest, 128 MB): 4x fp16 per entry =
//   lo u32 = half2( v[z,y,x],   v[z+1,y,x]   )
//   hi u32 = half2( v[z,y,x+1], v[z+1,y,x+1] )
// 8 corners from 2 LDG.64; fp16 x/y lerp; fp32 z-lerp + accumulate.
// 2 lanes per ray (interval halves) + shfl_xor(16) combine.
// vol in: [256,256,256] fp32 (z,y,x). out: [16,64,384] fp32.

#define NCOL 384
#define NROW 64
#define NVIEW 16
#define NSAMP 256

__device__ uint2 g_volQ[256 * 256 * 256];   // [y][x][z] fp16 quads, 128 MB

// pack two f32 -> f16x2 u32 (d = {hi, lo} per cvt semantics)
__device__ __forceinline__ unsigned int f2_to_h2(float hi, float lo) {
    unsigned int r;
    asm("cvt.rn.f16x2.f32 %0, %1, %2;" : "=r"(r) : "f"(hi), "f"(lo));
    return r;
}
// half2 (u32) -> two f32
__device__ __forceinline__ void h2_to_2f(unsigned int h2, float& lo, float& hi) {
    asm("{\n\t"
        ".reg .b16 l, h;\n\t"
        "mov.b32 {l, h}, %2;\n\t"
        "cvt.f32.f16 %0, l;\n\t"
        "cvt.f32.f16 %1, h;\n\t"
        "}" : "=f"(lo), "=f"(hi) : "r"(h2));
}
// ---- f16x2 math ----
__device__ __forceinline__ unsigned int hsub2(unsigned int a, unsigned int b) {
    unsigned int r;
    asm("sub.f16x2 %0, %1, %2;" : "=r"(r) : "r"(a), "r"(b));
    return r;
}
__device__ __forceinline__ unsigned int hfma2(unsigned int a, unsigned int b,
                                              unsigned int c) {
    unsigned int r;
    asm("fma.rn.f16x2 %0, %1, %2, %3;" : "=r"(r) : "r"(a), "r"(b), "r"(c));
    return r;
}

// prologue: vol[z][y][x] fp32 -> g_volQ[y][x][z] fp16 quads.
// Store phase emits uint4 (two consecutive z-quads) per STG.128.
__global__ void __launch_bounds__(256)
quad_build_kernel(const float* __restrict__ vol) {
    __shared__ float ts[33][33];               // [z local 0..32][x local 0..32]
    const int z0 = blockIdx.x * 32;
    const int x0 = blockIdx.y * 32;
    const int y  = blockIdx.z;
    const int t  = threadIdx.x;                // 0..255
    const int tx = t & 31;
    const int ty = t >> 5;                     // 0..7

    #pragma unroll
    for (int i = 0; i < 32; i += 8)
        ts[ty + i][tx] = vol[((z0 + ty + i) << 16) | (y << 8) | (x0 + tx)];
    if (ty == 0) {                             // extra z row
        const int z = z0 + 32;
        ts[32][tx] = (z < 256) ? vol[(z << 16) | (y << 8) | (x0 + tx)] : 0.0f;
    }
    if (ty == 1) {                             // extra x column
        const int x = x0 + 32;
        ts[tx][32] = (x < 256) ? vol[((z0 + tx) << 16) | (y << 8) | x] : 0.0f;
    }
    if (ty == 2 && tx == 0) {                  // corner
        const int z = z0 + 32, x = x0 + 32;
        ts[32][32] = (z < 256 && x < 256) ? vol[(z << 16) | (y << 8) | x] : 0.0f;
    }
    __syncthreads();

    // store: thread -> (z-pair zq 0..15, x-col xi 0..15); two x passes.
    const int zq = t & 15;                     // z = 2*zq, 2*zq+1
    const int xi = t >> 4;                     // 0..15
    const int z  = zq * 2;
    #pragma unroll
    for (int xo = 0; xo < 32; xo += 16) {
        const int xl = xi + xo;
        uint4 w;
        w.x = f2_to_h2(ts[z + 1][xl],     ts[z][xl]);          // quad z   .x
        w.y = f2_to_h2(ts[z + 1][xl + 1], ts[z][xl + 1]);      // quad z   .y
        w.z = f2_to_h2(ts[z + 2][xl],     ts[z + 1][xl]);      // quad z+1 .x
        w.w = f2_to_h2(ts[z + 2][xl + 1], ts[z + 1][xl + 1]);  // quad z+1 .y
        reinterpret_cast<uint4*>(g_volQ)
            [(y << 15) | ((x0 + xl) << 7) | ((z0 >> 1) + zq)] = w;
    }
}

// checked scalar fetch (boundary path): lo fp16 of lo word = v[z,y,x]
__device__ __forceinline__ float fetchS(int z, int y, int x) {
    if ((unsigned)x < 256u && (unsigned)y < 256u && (unsigned)z < 256u) {
        const unsigned int w =
            __ldg((const unsigned int*)g_volQ + (((y << 16) | (x << 8) | z) << 1));
        float v;
        asm("{\n\t.reg .b16 l, h;\n\tmov.b32 {l, h}, %1;\n\tcvt.f32.f16 %0, l;\n\t}"
            : "=f"(v) : "r"(w));
        return v;
    }
    return 0.0f;
}

// cold path: out of hot-loop register allocation
__device__ __noinline__ float trilerp_checked(float x, float y, float z) {
    const float xf = floorf(x), yf = floorf(y), zf = floorf(z);
    const float fx = x - xf, fy = y - yf, fz = z - zf;
    const int x0 = (int)xf, y0 = (int)yf, z0 = (int)zf;
    const float c000 = fetchS(z0,     y0,     x0);
    const float c001 = fetchS(z0,     y0,     x0 + 1);
    const float c010 = fetchS(z0,     y0 + 1, x0);
    const float c011 = fetchS(z0,     y0 + 1, x0 + 1);
    const float c100 = fetchS(z0 + 1, y0,     x0);
    const float c101 = fetchS(z0 + 1, y0,     x0 + 1);
    const float c110 = fetchS(z0 + 1, y0 + 1, x0);
    const float c111 = fetchS(z0 + 1, y0 + 1, x0 + 1);
    const float gx = 1.0f - fx, gy = 1.0f - fy, gz = 1.0f - fz;
    const float v00 = gx * c000 + fx * c001;
    const float v01 = gx * c010 + fx * c011;
    const float v10 = gx * c100 + fx * c101;
    const float v11 = gx * c110 + fx * c111;
    const float v0  = gy * v00 + fy * v01;
    const float v1  = gy * v10 + fy * v11;
    return gz * v0 + fz * v1;
}

__global__ void __launch_bounds__(256, 6)
proj_kernel(const float* __restrict__ angles,
            float* __restrict__ out) {
    const int tidx = blockIdx.x * blockDim.x + threadIdx.x;
    const int lane = threadIdx.x & 31;
    const int half = lane >> 4;                       // 0 = first half, 1 = second
    const int rid  = (tidx >> 5) * 16 + (lane & 15);  // 16 rays/warp, 2 lanes each
    const int row  = rid & 63;
    const int col  = (rid >> 6) % NCOL;
    const int view = rid / (64 * NCOL);

    const float DET_U = 1.2f, DET_V = 1.2f;
    const float ISO = 500.0f, SDD = 1000.0f;
    const float RAY_LEN = 1.7320508075688772f * 256.0f;
    const float DT = RAY_LEN / (float)NSAMP;   // sqrt(3)

    const float beta = angles[view];
    const float cb = cosf(beta);
    const float sb = sinf(beta);

    const float u = ((float)col - NCOL * 0.5f + 0.5f) * DET_U;
    const float v = ((float)row - NROW * 0.5f + 0.5f) * DET_V;

    const float sx = ISO * cb;
    const float sy = ISO * sb;
    float dx = -(SDD - ISO) * cb - u * sb - sx;
    float dy = -(SDD - ISO) * sb + u * cb - sy;
    float dz = v;
    const float inv = rsqrtf(dx * dx + dy * dy + dz * dz);
    dx *= inv; dy *= inv; dz *= inv;

    const float t0 = ISO - RAY_LEN * 0.5f + 0.5f * DT;

    // outer clip (all coords in (-128.5,128.5)) and inner fully-interior clip
    float tmin = -1e30f, tmax = 1e30f;
    float t2mn = -1e30f, t2mx = 1e30f;
    {
        const float s0[3] = {sx, sy, 0.0f};
        const float dd[3] = {dx, dy, dz};
        #pragma unroll
        for (int ax = 0; ax < 3; ++ax) {
            if (fabsf(dd[ax]) > 1e-12f) {
                const float r = 1.0f / dd[ax];
                float ta = (-128.5f - s0[ax]) * r;
                float tb = ( 128.5f - s0[ax]) * r;
                tmin = fmaxf(tmin, fminf(ta, tb));
                tmax = fminf(tmax, fmaxf(ta, tb));
                ta = (-127.49f - s0[ax]) * r;
                tb = ( 127.49f - s0[ax]) * r;
                t2mn = fmaxf(t2mn, fminf(ta, tb));
                t2mx = fminf(t2mx, fmaxf(ta, tb));
            } else {
                if (s0[ax] <= -128.5f  || s0[ax] >= 128.5f)  tmax = tmin - 1.0f;
                if (s0[ax] <  -127.49f || s0[ax] >  127.49f) t2mx = t2mn - 1.0f;
            }
        }
    }
    int s_lo = max((int)floorf((tmin - t0) / DT), 0);
    int s_hi = min((int)ceilf ((tmax - t0) / DT) + 1, NSAMP - 1);
    int i_lo = max((int)ceilf ((t2mn - t0) / DT), s_lo);
    int i_hi = min((int)floorf((t2mx - t0) / DT), s_hi);
    if (i_lo > i_hi) { i_lo = s_hi + 1; i_hi = s_hi; }

    const float ax0 = fmaf(t0, dx, sx) + 127.5f;
    const float ay0 = fmaf(t0, dy, sy) + 127.5f;
    const float az0 = fmaf(t0, dz, 0.0f) + 127.5f;
    const float axs = DT * dx, ays = DT * dy, azs = DT * dz;

    // split interior at midpoint; half0 also does head, half1 also does tail
    const int smid = (i_lo + i_hi + 1) >> 1;
    const int my_ilo = half ? smid : i_lo;
    const int my_ihi = half ? i_hi : (smid - 1);

    float acc = 0.0f;

    if (half == 0) {
        float fs = (float)s_lo;
        for (int s = s_lo; s < i_lo; ++s, fs += 1.0f) {
            acc += trilerp_checked(fmaf(fs, axs, ax0), fmaf(fs, ays, ay0),
                                   fmaf(fs, azs, az0));
        }
    } else {
        float fs = (float)(i_hi + 1);
        for (int s = i_hi + 1; s <= s_hi; ++s, fs += 1.0f) {
            acc += trilerp_checked(fmaf(fs, axs, ax0), fmaf(fs, ays, ay0),
                                   fmaf(fs, azs, az0));
        }
    }

    // interior: 2x LDG.64, fp16 x+y lerp, single h2->f32, fp32 z-lerp/acc.
    // Float sample counter (exact for integers) removes per-sample I2F.
    float fs = (float)my_ilo;
    #pragma unroll 4
    for (int s = my_ilo; s <= my_ihi; ++s, fs += 1.0f) {
        const float x = fmaf(fs, axs, ax0);
        const float y = fmaf(fs, ays, ay0);
        const float z = fmaf(fs, azs, az0);

        const float xf = floorf(x), yf = floorf(y), zf = floorf(z);
        const float fx = x - xf, fy = y - yf, fz = z - zf;

        // fused float-domain index (exact: integers < 2^24), quad strides
        const int idx = (int)fmaf(yf, 65536.0f, fmaf(xf, 256.0f, zf));

        const uint2* p = g_volQ + idx;
        const uint2 q0 = __ldg(p);             // y0   : z-pairs @ x0, x0+1
        const uint2 q1 = __ldg(p + 65536);     // y0+1 : z-pairs @ x0, x0+1

        // x-lerp in f16x2: v = a + fx*(b-a)
        const unsigned int fxh = f2_to_h2(fx, fx);
        const unsigned int v0h = hfma2(fxh, hsub2(q0.y, q0.x), q0.x);
        const unsigned int v1h = hfma2(fxh, hsub2(q1.y, q1.x), q1.x);

        // y-lerp in f16x2
        const unsigned int fyh = f2_to_h2(fy, fy);
        const unsigned int vvh = hfma2(fyh, hsub2(v1h, v0h), v0h);

        // single conversion, scalar fp32 z-lerp + accumulate
        float vlo, vhi;
        h2_to_2f(vvh, vlo, vhi);
        acc = fmaf(fz, vhi - vlo, acc + vlo);
    }

    // combine the two halves of each ray and write once
    acc += __shfl_xor_sync(0xffffffffu, acc, 16);
    if (half == 0)
        out[(view * NROW + row) * NCOL + col] = acc * DT;
}

extern "C" void kernel_launch(void* const* d_in, const int* in_sizes, int n_in,
                              void* d_out, int out_size) {
    const float* img = (const float*)d_in[0];
    const float* ang = (const float*)d_in[1];
    if (n_in >= 2 && in_sizes[0] < in_sizes[1]) {
        img = (const float*)d_in[1];
        ang = (const float*)d_in[0];
    }
    float* out = (float*)d_out;

    dim3 tb(256, 1, 1);
    dim3 tg(8, 8, 256);            // (z-tiles, x-tiles, y)
    quad_build_kernel<<<tg, tb>>>(img);

    const int total_threads = NVIEW * NROW * NCOL * 2;  // 786432 (2 lanes/ray)
    proj_kernel<<<total_threads / 256, 256>>>(ang, out);
}